// round 10
// baseline (speedup 1.0000x reference)
#include <cuda_runtime.h>
#include <cuda_fp16.h>
#include <math.h>

#define N_NODES 100000
#define N_EDGES 1600000
#define IN_C 64
#define HID_C 64
#define OUT_C 40
#define SCAN_BS 512
#define SCAN_NB ((N_NODES + SCAN_BS - 1) / SCAN_BS)   // 196

// Scratch (allocation-free rule: __device__ globals)
__device__ uint2 g_tmph[(size_t)N_NODES * (HID_C / 4)]; // fp16 messages (layers 1,2)
__device__ float g_tmp[(size_t)N_NODES * HID_C];        // fp32 messages (layer 3)
__device__ float g_h[(size_t)N_NODES * HID_C];          // aggregated layer output / next input
__device__ float g_dinv[N_NODES];
__device__ int   g_deg[N_NODES];
__device__ int   g_rowptr[N_NODES + 1];
__device__ int   g_cursor[N_NODES];
__device__ int   g_bsum[SCAN_NB];
__device__ int2  g_epair[N_EDGES];                 // {src, norm(bits)} binned by dst

// ---------------------------------------------------------------------------
// packed f32x2 helpers (Blackwell: 1 instr = 2 fp32 MACs)
// ---------------------------------------------------------------------------
__device__ __forceinline__ void fma2(unsigned long long& d, unsigned long long a,
                                     unsigned long long b) {
    asm("fma.rn.f32x2 %0, %1, %2, %0;" : "+l"(d) : "l"(a), "l"(b));
}
__device__ __forceinline__ unsigned long long bcast2(float x) {
    unsigned long long p;
    asm("mov.b64 %0, {%1, %1};" : "=l"(p) : "f"(x));
    return p;
}
__device__ __forceinline__ unsigned long long pair2(float lo, float hi) {
    unsigned long long p;
    asm("mov.b64 %0, {%1, %2};" : "=l"(p) : "f"(lo), "f"(hi));
    return p;
}
__device__ __forceinline__ void unpack2(unsigned long long p, float& lo, float& hi) {
    asm("mov.b64 {%0, %1}, %2;" : "=f"(lo), "=f"(hi) : "l"(p));
}

// ---------------------------------------------------------------------------
// degree
// ---------------------------------------------------------------------------
__global__ void deg_kernel(const int* __restrict__ dst, int E) {
    int i = blockIdx.x * blockDim.x + threadIdx.x;
    if (i < E) atomicAdd(&g_deg[dst[i]], 1);
}

// ---------------------------------------------------------------------------
// CSR build: block-wise exclusive scan of deg -> rowptr (dinv fused here)
// ---------------------------------------------------------------------------
__global__ void scan_block_kernel(int N) {
    __shared__ int s[SCAN_BS];
    int i = blockIdx.x * SCAN_BS + threadIdx.x;
    int v = (i < N) ? g_deg[i] : 0;
    if (i < N) g_dinv[i] = rsqrtf((float)(v + 1));     // +1 self loop; always > 0
    s[threadIdx.x] = v;
    __syncthreads();
#pragma unroll
    for (int off = 1; off < SCAN_BS; off <<= 1) {
        int t = 0;
        if (threadIdx.x >= off) t = s[threadIdx.x - off];
        __syncthreads();
        if (threadIdx.x >= off) s[threadIdx.x] += t;
        __syncthreads();
    }
    if (i < N) g_rowptr[i] = s[threadIdx.x] - v;       // exclusive, block-local
    if (threadIdx.x == SCAN_BS - 1) g_bsum[blockIdx.x] = s[SCAN_BS - 1];
}

// add block offsets (each block redundantly scans the 196 block sums in smem)
__global__ void add_off_kernel(int N, int E) {
    __shared__ int s[256];
    int t = threadIdx.x;
    int v = (t < SCAN_NB) ? g_bsum[t] : 0;
    s[t] = v;
    __syncthreads();
#pragma unroll
    for (int off = 1; off < 256; off <<= 1) {
        int u = 0;
        if (t >= off) u = s[t - off];
        __syncthreads();
        if (t >= off) s[t] += u;
        __syncthreads();
    }
    int i = blockIdx.x * blockDim.x + threadIdx.x;
    if (i < N) {
        int b = i >> 9;
        int off = (b > 0) ? s[b - 1] : 0;          // exclusive prefix of bsum
        int r = g_rowptr[i] + off;
        g_rowptr[i] = r;
        g_cursor[i] = r;
    }
    if (i == 0) g_rowptr[N] = E;
}

__global__ void fill_kernel(const int* __restrict__ src, const int* __restrict__ dst, int E) {
    int e = blockIdx.x * blockDim.x + threadIdx.x;
    if (e >= E) return;
    int s = src[e], d = dst[e];
    float nrm = g_dinv[s] * g_dinv[d];
    int pos = atomicAdd(&g_cursor[d], 1);
    g_epair[pos] = make_int2(s, __float_as_int(nrm));
}

// ---------------------------------------------------------------------------
// dense transform, fp32 output (layer 3)
// ---------------------------------------------------------------------------
template <int IN, int OUT, bool RELU>
__global__ void __launch_bounds__(256) gemm_kernel(const float* __restrict__ X,
                                                   const float* __restrict__ W,
                                                   float* __restrict__ Y, int N) {
    constexpr int NJ = OUT / 8;
    __shared__ __align__(16) float Ws[IN * OUT];
    for (int i = threadIdx.x; i < IN * OUT; i += blockDim.x) Ws[i] = W[i];
    __syncthreads();

    int half = threadIdx.x & 1;
    int r = blockIdx.x * 128 + (threadIdx.x >> 1);
    if (r >= N) return;

    unsigned long long acc[2 * NJ];
#pragma unroll
    for (int j = 0; j < 2 * NJ; j++) acc[j] = 0ull;

    const float4* xr = reinterpret_cast<const float4*>(X + (size_t)r * IN);
#pragma unroll 4
    for (int k4 = 0; k4 < IN / 4; k4++) {
        float4 xv = xr[k4];
        if (RELU) {
            xv.x = fmaxf(xv.x, 0.f); xv.y = fmaxf(xv.y, 0.f);
            xv.z = fmaxf(xv.z, 0.f); xv.w = fmaxf(xv.w, 0.f);
        }
        float xs[4] = {xv.x, xv.y, xv.z, xv.w};
#pragma unroll
        for (int kk = 0; kk < 4; kk++) {
            unsigned long long xx = bcast2(xs[kk]);
            const float4* wr = reinterpret_cast<const float4*>(Ws + (4 * k4 + kk) * OUT);
#pragma unroll
            for (int j = 0; j < NJ; j++) {
                float4 w = wr[2 * j + half];
                fma2(acc[2 * j],     xx, pair2(w.x, w.y));
                fma2(acc[2 * j + 1], xx, pair2(w.z, w.w));
            }
        }
    }
    float4* yr = reinterpret_cast<float4*>(Y + (size_t)r * OUT);
#pragma unroll
    for (int j = 0; j < NJ; j++) {
        float4 o;
        unpack2(acc[2 * j],     o.x, o.y);
        unpack2(acc[2 * j + 1], o.z, o.w);
        yr[2 * j + half] = o;
    }
}

// ---------------------------------------------------------------------------
// dense transform, fp16 output (layers 1,2; OUT=64)
// ---------------------------------------------------------------------------
template <int IN, bool RELU>
__global__ void __launch_bounds__(256) gemmh_kernel(const float* __restrict__ X,
                                                    const float* __restrict__ W,
                                                    uint2* __restrict__ Yh, int N) {
    constexpr int OUT = HID_C;
    constexpr int NJ = OUT / 8;   // 8
    __shared__ __align__(16) float Ws[IN * OUT];
    for (int i = threadIdx.x; i < IN * OUT; i += blockDim.x) Ws[i] = W[i];
    __syncthreads();

    int half = threadIdx.x & 1;
    int r = blockIdx.x * 128 + (threadIdx.x >> 1);
    if (r >= N) return;

    unsigned long long acc[2 * NJ];
#pragma unroll
    for (int j = 0; j < 2 * NJ; j++) acc[j] = 0ull;

    const float4* xr = reinterpret_cast<const float4*>(X + (size_t)r * IN);
#pragma unroll 4
    for (int k4 = 0; k4 < IN / 4; k4++) {
        float4 xv = xr[k4];
        if (RELU) {
            xv.x = fmaxf(xv.x, 0.f); xv.y = fmaxf(xv.y, 0.f);
            xv.z = fmaxf(xv.z, 0.f); xv.w = fmaxf(xv.w, 0.f);
        }
        float xs[4] = {xv.x, xv.y, xv.z, xv.w};
#pragma unroll
        for (int kk = 0; kk < 4; kk++) {
            unsigned long long xx = bcast2(xs[kk]);
            const float4* wr = reinterpret_cast<const float4*>(Ws + (4 * k4 + kk) * OUT);
#pragma unroll
            for (int j = 0; j < NJ; j++) {
                float4 w = wr[2 * j + half];
                fma2(acc[2 * j],     xx, pair2(w.x, w.y));
                fma2(acc[2 * j + 1], xx, pair2(w.z, w.w));
            }
        }
    }
    uint2* yr = Yh + (size_t)r * (OUT / 4);   // 16 uint2 per row
#pragma unroll
    for (int j = 0; j < NJ; j++) {
        float l0, h0, l1, h1;
        unpack2(acc[2 * j],     l0, h0);
        unpack2(acc[2 * j + 1], l1, h1);
        __half2 a = __floats2half2_rn(l0, h0);
        __half2 b = __floats2half2_rn(l1, h1);
        uint2 o;
        o.x = *reinterpret_cast<unsigned int*>(&a);
        o.y = *reinterpret_cast<unsigned int*>(&b);
        yr[2 * j + half] = o;
    }
}

__device__ __forceinline__ float4 h4_to_f4(uint2 raw) {
    __half2 a = *reinterpret_cast<__half2*>(&raw.x);
    __half2 b = *reinterpret_cast<__half2*>(&raw.y);
    float2 fa = __half22float2(a);
    float2 fb = __half22float2(b);
    return make_float4(fa.x, fa.y, fb.x, fb.y);
}

// ---------------------------------------------------------------------------
// CSR aggregate over fp16 messages (layers 1,2), shfl-batched edges:
// lane-parallel coalesced epair load (16 edges/load), then width-16 shfl
// broadcast -> 16 independent gathers in flight per row-group.
// ---------------------------------------------------------------------------
__global__ void aggregateh_kernel(const uint2* __restrict__ th, const float* __restrict__ b,
                                  float* __restrict__ outp, int N) {
    int g    = blockIdx.x * 16 + (threadIdx.x >> 4);
    int lane = threadIdx.x & 15;
    unsigned submask = 0xffffu << ((threadIdx.x & 31) & 16);
    bool rowok = (g < N);
    int row  = rowok ? g : 0;

    const float4* b4 = reinterpret_cast<const float4*>(b);

    float4 acc = make_float4(0.f, 0.f, 0.f, 0.f);
    int beg = 0, end = 0;
    if (rowok) {
        beg = g_rowptr[row];
        end = g_rowptr[row + 1];

        float di = g_dinv[row];
        float s2 = di * di;
        float4 t = h4_to_f4(__ldg(&th[(size_t)row * 16 + lane]));
        float4 bb = b4[lane];
        acc.x = bb.x + s2 * t.x; acc.y = bb.y + s2 * t.y;
        acc.z = bb.z + s2 * t.z; acc.w = bb.w + s2 * t.w;
    }

    for (int base = beg; base < end; base += 16) {
        int left = end - base;
        int2 p = make_int2(0, 0);
        if (lane < left) p = __ldg(&g_epair[base + lane]);
        if (left >= 16) {
#pragma unroll
            for (int k = 0; k < 16; k++) {
                int   s = __shfl_sync(submask, p.x, k, 16);
                float n = __int_as_float(__shfl_sync(submask, p.y, k, 16));
                float4 v = h4_to_f4(__ldg(&th[(size_t)s * 16 + lane]));
                acc.x += n * v.x; acc.y += n * v.y;
                acc.z += n * v.z; acc.w += n * v.w;
            }
        } else {
            for (int k = 0; k < left; k++) {
                int   s = __shfl_sync(submask, p.x, k, 16);
                float n = __int_as_float(__shfl_sync(submask, p.y, k, 16));
                float4 v = h4_to_f4(__ldg(&th[(size_t)s * 16 + lane]));
                acc.x += n * v.x; acc.y += n * v.y;
                acc.z += n * v.z; acc.w += n * v.w;
            }
        }
    }

    if (rowok)
        reinterpret_cast<float4*>(outp)[(size_t)row * 16 + lane] = acc;
}

// ---------------------------------------------------------------------------
// CSR aggregate fp32 + fused log_softmax (layer 3), shfl-batched edges
// ---------------------------------------------------------------------------
template <int C4>
__global__ void aggregate_lsm_kernel(const float* __restrict__ tmp, const float* __restrict__ b,
                                     float* __restrict__ outp, int N) {
    int g    = blockIdx.x * 16 + (threadIdx.x >> 4);
    int lane = threadIdx.x & 15;
    unsigned submask = 0xffffu << ((threadIdx.x & 31) & 16);
    bool rowok = (g < N);
    int row  = rowok ? g : 0;
    bool act = rowok && (lane < C4);

    const float4* t4 = reinterpret_cast<const float4*>(tmp);
    const float4* b4 = reinterpret_cast<const float4*>(b);

    float4 acc = make_float4(0.f, 0.f, 0.f, 0.f);
    int beg = 0, end = 0;
    if (rowok) {
        beg = g_rowptr[row];
        end = g_rowptr[row + 1];
    }
    if (act) {
        float di = g_dinv[row];
        float s2 = di * di;
        float4 t = t4[(size_t)row * C4 + lane];
        float4 bb = b4[lane];
        acc.x = bb.x + s2 * t.x; acc.y = bb.y + s2 * t.y;
        acc.z = bb.z + s2 * t.z; acc.w = bb.w + s2 * t.w;
    }

    for (int base = beg; base < end; base += 16) {
        int left = end - base;
        int2 p = make_int2(0, 0);
        if (lane < left) p = __ldg(&g_epair[base + lane]);
        if (left >= 16) {
#pragma unroll
            for (int k = 0; k < 16; k++) {
                int   s = __shfl_sync(submask, p.x, k, 16);
                float n = __int_as_float(__shfl_sync(submask, p.y, k, 16));
                if (act) {
                    float4 v = __ldg(&t4[(size_t)s * C4 + lane]);
                    acc.x += n * v.x; acc.y += n * v.y;
                    acc.z += n * v.z; acc.w += n * v.w;
                }
            }
        } else {
            for (int k = 0; k < left; k++) {
                int   s = __shfl_sync(submask, p.x, k, 16);
                float n = __int_as_float(__shfl_sync(submask, p.y, k, 16));
                if (act) {
                    float4 v = __ldg(&t4[(size_t)s * C4 + lane]);
                    acc.x += n * v.x; acc.y += n * v.y;
                    acc.z += n * v.z; acc.w += n * v.w;
                }
            }
        }
    }

    // row-wise log_softmax across the 16-lane group
    float m = act ? fmaxf(fmaxf(acc.x, acc.y), fmaxf(acc.z, acc.w)) : -INFINITY;
#pragma unroll
    for (int k = 8; k >= 1; k >>= 1)
        m = fmaxf(m, __shfl_xor_sync(0xffffffffu, m, k, 16));
    float s = act ? (__expf(acc.x - m) + __expf(acc.y - m) +
                     __expf(acc.z - m) + __expf(acc.w - m)) : 0.f;
#pragma unroll
    for (int k = 8; k >= 1; k >>= 1)
        s += __shfl_xor_sync(0xffffffffu, s, k, 16);
    float l = m + logf(s);
    if (act) {
        reinterpret_cast<float4*>(outp)[(size_t)row * C4 + lane] =
            make_float4(acc.x - l, acc.y - l, acc.z - l, acc.w - l);
    }
}

// ---------------------------------------------------------------------------
// launcher: CSR build on default stream, layer-1 GEMM forked onto s2
// ---------------------------------------------------------------------------
extern "C" void kernel_launch(void* const* d_in, const int* in_sizes, int n_in,
                              void* d_out, int out_size) {
    const float* x  = (const float*)d_in[0];
    const int*   ei = (const int*)d_in[1];
    const float* W1 = (const float*)d_in[2];
    const float* b1 = (const float*)d_in[3];
    const float* Wh = (const float*)d_in[4];
    const float* bh = (const float*)d_in[5];
    const float* W2 = (const float*)d_in[6];
    const float* b2 = (const float*)d_in[7];
    float* out = (float*)d_out;

    int N = in_sizes[0] / IN_C;
    int E = in_sizes[1] / 2;
    const int* src = ei;
    const int* dst = ei + E;

    float *p_tmp, *p_h;
    uint2* p_tmph;
    int* p_deg;
    cudaGetSymbolAddress((void**)&p_tmp, g_tmp);
    cudaGetSymbolAddress((void**)&p_h, g_h);
    cudaGetSymbolAddress((void**)&p_tmph, g_tmph);
    cudaGetSymbolAddress((void**)&p_deg, g_deg);

    static cudaStream_t s2 = nullptr;
    static cudaEvent_t evFork = nullptr, evJoin = nullptr;
    if (!s2) {
        cudaStreamCreateWithFlags(&s2, cudaStreamNonBlocking);
        cudaEventCreateWithFlags(&evFork, cudaEventDisableTiming);
        cudaEventCreateWithFlags(&evJoin, cudaEventDisableTiming);
    }

    const int T = 256;
    int nb_N = (N + T - 1) / T;
    int nb_E = (E + T - 1) / T;
    int nb_G = (N + 127) / 128;   // gemm: 128 rows/block
    int nb_A = (N + 15) / 16;     // aggregate: 16 rows/block

    // ---- fork: layer-1 GEMM (fp16 out) on s2, overlapping CSR build ----
    cudaEventRecord(evFork, 0);
    cudaStreamWaitEvent(s2, evFork, 0);
    gemmh_kernel<IN_C, false><<<nb_G, T, 0, s2>>>(x, W1, p_tmph, N);
    cudaEventRecord(evJoin, s2);

    // ---- CSR build on default stream ----
    cudaMemsetAsync(p_deg, 0, (size_t)N * sizeof(int), 0);
    deg_kernel<<<nb_E, T>>>(dst, E);
    scan_block_kernel<<<SCAN_NB, SCAN_BS>>>(N);   // also computes dinv
    add_off_kernel<<<nb_N, T>>>(N, E);            // folds block-sum prefix in
    fill_kernel<<<nb_E, T>>>(src, dst, E);

    // ---- layer 1: aggregate fp16 messages -> fp32 h ----
    cudaStreamWaitEvent(0, evJoin, 0);
    aggregateh_kernel<<<nb_A, T>>>(p_tmph, b1, p_h, N);

    // ---- layer 2 ----
    gemmh_kernel<HID_C, true><<<nb_G, T>>>(p_h, Wh, p_tmph, N);
    aggregateh_kernel<<<nb_A, T>>>(p_tmph, bh, p_h, N);

    // ---- layer 3 (40-wide, fp32) + fused log_softmax ----
    gemm_kernel<HID_C, OUT_C, true><<<nb_G, T>>>(p_h, W2, p_tmp, N);
    aggregate_lsm_kernel<OUT_C / 4><<<nb_A, T>>>(p_tmp, b2, out, N);
}

// round 11
// speedup vs baseline: 1.1649x; 1.1649x over previous
#include <cuda_runtime.h>
#include <cuda_fp16.h>
#include <math.h>

#define N_NODES 100000
#define N_EDGES 1600000
#define IN_C 64
#define HID_C 64
#define OUT_C 40
#define SCAN_BS 512
#define SCAN_NB ((N_NODES + SCAN_BS - 1) / SCAN_BS)   // 196

// Scratch (allocation-free rule: __device__ globals)
__device__ uint2 g_tmph[(size_t)N_NODES * (HID_C / 4)]; // fp16 messages (all layers)
__device__ float g_h[(size_t)N_NODES * HID_C];          // aggregated layer output / next input
__device__ float g_dinv[N_NODES];
__device__ int   g_deg[N_NODES];
__device__ int   g_rowptr[N_NODES + 1];
__device__ int   g_cursor[N_NODES];
__device__ int   g_bsum[SCAN_NB];
__device__ int2  g_epair[N_EDGES];                 // {src, norm(bits)} binned by dst

// ---------------------------------------------------------------------------
// packed f32x2 helpers (Blackwell: 1 instr = 2 fp32 MACs)
// ---------------------------------------------------------------------------
__device__ __forceinline__ void fma2(unsigned long long& d, unsigned long long a,
                                     unsigned long long b) {
    asm("fma.rn.f32x2 %0, %1, %2, %0;" : "+l"(d) : "l"(a), "l"(b));
}
__device__ __forceinline__ unsigned long long bcast2(float x) {
    unsigned long long p;
    asm("mov.b64 %0, {%1, %1};" : "=l"(p) : "f"(x));
    return p;
}
__device__ __forceinline__ unsigned long long pair2(float lo, float hi) {
    unsigned long long p;
    asm("mov.b64 %0, {%1, %2};" : "=l"(p) : "f"(lo), "f"(hi));
    return p;
}
__device__ __forceinline__ void unpack2(unsigned long long p, float& lo, float& hi) {
    asm("mov.b64 {%0, %1}, %2;" : "=f"(lo), "=f"(hi) : "l"(p));
}

// ---------------------------------------------------------------------------
// degree
// ---------------------------------------------------------------------------
__global__ void deg_kernel(const int* __restrict__ dst, int E) {
    int i = blockIdx.x * blockDim.x + threadIdx.x;
    if (i < E) atomicAdd(&g_deg[dst[i]], 1);
}

// ---------------------------------------------------------------------------
// CSR build: block-wise exclusive scan of deg -> rowptr (dinv fused here)
// ---------------------------------------------------------------------------
__global__ void scan_block_kernel(int N) {
    __shared__ int s[SCAN_BS];
    int i = blockIdx.x * SCAN_BS + threadIdx.x;
    int v = (i < N) ? g_deg[i] : 0;
    if (i < N) g_dinv[i] = rsqrtf((float)(v + 1));     // +1 self loop; always > 0
    s[threadIdx.x] = v;
    __syncthreads();
#pragma unroll
    for (int off = 1; off < SCAN_BS; off <<= 1) {
        int t = 0;
        if (threadIdx.x >= off) t = s[threadIdx.x - off];
        __syncthreads();
        if (threadIdx.x >= off) s[threadIdx.x] += t;
        __syncthreads();
    }
    if (i < N) g_rowptr[i] = s[threadIdx.x] - v;       // exclusive, block-local
    if (threadIdx.x == SCAN_BS - 1) g_bsum[blockIdx.x] = s[SCAN_BS - 1];
}

// add block offsets (each block redundantly scans the 196 block sums in smem)
__global__ void add_off_kernel(int N, int E) {
    __shared__ int s[256];
    int t = threadIdx.x;
    int v = (t < SCAN_NB) ? g_bsum[t] : 0;
    s[t] = v;
    __syncthreads();
#pragma unroll
    for (int off = 1; off < 256; off <<= 1) {
        int u = 0;
        if (t >= off) u = s[t - off];
        __syncthreads();
        if (t >= off) s[t] += u;
        __syncthreads();
    }
    int i = blockIdx.x * blockDim.x + threadIdx.x;
    if (i < N) {
        int b = i >> 9;
        int off = (b > 0) ? s[b - 1] : 0;          // exclusive prefix of bsum
        int r = g_rowptr[i] + off;
        g_rowptr[i] = r;
        g_cursor[i] = r;
    }
    if (i == 0) g_rowptr[N] = E;
}

__global__ void fill_kernel(const int* __restrict__ src, const int* __restrict__ dst, int E) {
    int e = blockIdx.x * blockDim.x + threadIdx.x;
    if (e >= E) return;
    int s = src[e], d = dst[e];
    float nrm = g_dinv[s] * g_dinv[d];
    int pos = atomicAdd(&g_cursor[d], 1);
    g_epair[pos] = make_int2(s, __float_as_int(nrm));
}

// ---------------------------------------------------------------------------
// dense transform, fp16 output: fp32 f32x2 accumulate, one rounding on store.
// 2 threads/row, interleaved chunks. Row = OUT/4 uint2 (4 halves each).
// ---------------------------------------------------------------------------
template <int IN, int OUT, bool RELU>
__global__ void __launch_bounds__(256) gemmh_kernel(const float* __restrict__ X,
                                                    const float* __restrict__ W,
                                                    uint2* __restrict__ Yh, int N) {
    constexpr int NJ = OUT / 8;   // float4 chunks per thread (8 for 64, 5 for 40)
    __shared__ __align__(16) float Ws[IN * OUT];
    for (int i = threadIdx.x; i < IN * OUT; i += blockDim.x) Ws[i] = W[i];
    __syncthreads();

    int half = threadIdx.x & 1;
    int r = blockIdx.x * 128 + (threadIdx.x >> 1);
    if (r >= N) return;

    unsigned long long acc[2 * NJ];
#pragma unroll
    for (int j = 0; j < 2 * NJ; j++) acc[j] = 0ull;

    const float4* xr = reinterpret_cast<const float4*>(X + (size_t)r * IN);
#pragma unroll 4
    for (int k4 = 0; k4 < IN / 4; k4++) {
        float4 xv = xr[k4];
        if (RELU) {
            xv.x = fmaxf(xv.x, 0.f); xv.y = fmaxf(xv.y, 0.f);
            xv.z = fmaxf(xv.z, 0.f); xv.w = fmaxf(xv.w, 0.f);
        }
        float xs[4] = {xv.x, xv.y, xv.z, xv.w};
#pragma unroll
        for (int kk = 0; kk < 4; kk++) {
            unsigned long long xx = bcast2(xs[kk]);
            const float4* wr = reinterpret_cast<const float4*>(Ws + (4 * k4 + kk) * OUT);
#pragma unroll
            for (int j = 0; j < NJ; j++) {
                float4 w = wr[2 * j + half];
                fma2(acc[2 * j],     xx, pair2(w.x, w.y));
                fma2(acc[2 * j + 1], xx, pair2(w.z, w.w));
            }
        }
    }
    uint2* yr = Yh + (size_t)r * (OUT / 4);
#pragma unroll
    for (int j = 0; j < NJ; j++) {
        float l0, h0, l1, h1;
        unpack2(acc[2 * j],     l0, h0);
        unpack2(acc[2 * j + 1], l1, h1);
        __half2 a = __floats2half2_rn(l0, h0);
        __half2 b = __floats2half2_rn(l1, h1);
        uint2 o;
        o.x = *reinterpret_cast<unsigned int*>(&a);
        o.y = *reinterpret_cast<unsigned int*>(&b);
        yr[2 * j + half] = o;
    }
}

__device__ __forceinline__ float4 h4_to_f4(uint2 raw) {
    __half2 a = *reinterpret_cast<__half2*>(&raw.x);
    __half2 b = *reinterpret_cast<__half2*>(&raw.y);
    float2 fa = __half22float2(a);
    float2 fb = __half22float2(b);
    return make_float4(fa.x, fa.y, fb.x, fb.y);
}

// ---------------------------------------------------------------------------
// CSR aggregate over fp16 messages (round-9 proven loop structure):
// 16 lanes per row, lane handles 4 channels (one uint2); fp32 accumulate;
// 4-way edge unroll. Fused self-loop/bias init; optional fused log_softmax.
// ---------------------------------------------------------------------------
template <int C4, bool LSM>
__global__ void aggregateh_kernel(const uint2* __restrict__ th, const float* __restrict__ b,
                                  float* __restrict__ outp, int N) {
    int g    = blockIdx.x * 16 + (threadIdx.x >> 4);
    int lane = threadIdx.x & 15;
    bool rowok = (g < N);
    int row  = rowok ? g : 0;
    bool act = rowok && (lane < C4);

    const float4* b4 = reinterpret_cast<const float4*>(b);

    float4 acc = make_float4(0.f, 0.f, 0.f, 0.f);
    int beg = 0, end = 0;
    if (rowok) {
        beg = g_rowptr[row];
        end = g_rowptr[row + 1];
    }
    if (act) {
        float di = g_dinv[row];
        float s2 = di * di;
        float4 t = h4_to_f4(__ldg(&th[(size_t)row * C4 + lane]));
        float4 bb = b4[lane];
        acc.x = bb.x + s2 * t.x; acc.y = bb.y + s2 * t.y;
        acc.z = bb.z + s2 * t.z; acc.w = bb.w + s2 * t.w;
    }

    int j = beg;
    for (; j + 3 < end; j += 4) {                       // 4-way unroll for MLP
        int2 p0 = __ldg(&g_epair[j]);
        int2 p1 = __ldg(&g_epair[j + 1]);
        int2 p2 = __ldg(&g_epair[j + 2]);
        int2 p3 = __ldg(&g_epair[j + 3]);
        if (act) {
            float4 v0 = h4_to_f4(__ldg(&th[(size_t)p0.x * C4 + lane]));
            float4 v1 = h4_to_f4(__ldg(&th[(size_t)p1.x * C4 + lane]));
            float4 v2 = h4_to_f4(__ldg(&th[(size_t)p2.x * C4 + lane]));
            float4 v3 = h4_to_f4(__ldg(&th[(size_t)p3.x * C4 + lane]));
            float n0 = __int_as_float(p0.y), n1 = __int_as_float(p1.y);
            float n2 = __int_as_float(p2.y), n3 = __int_as_float(p3.y);
            acc.x += n0 * v0.x + n1 * v1.x + n2 * v2.x + n3 * v3.x;
            acc.y += n0 * v0.y + n1 * v1.y + n2 * v2.y + n3 * v3.y;
            acc.z += n0 * v0.z + n1 * v1.z + n2 * v2.z + n3 * v3.z;
            acc.w += n0 * v0.w + n1 * v1.w + n2 * v2.w + n3 * v3.w;
        }
    }
    for (; j < end; j++) {
        int2 p0 = __ldg(&g_epair[j]);
        if (act) {
            float4 v0 = h4_to_f4(__ldg(&th[(size_t)p0.x * C4 + lane]));
            float n0 = __int_as_float(p0.y);
            acc.x += n0 * v0.x; acc.y += n0 * v0.y;
            acc.z += n0 * v0.z; acc.w += n0 * v0.w;
        }
    }

    if (LSM) {
        // row-wise log_softmax across the 16-lane group (width-16 butterfly)
        float m = act ? fmaxf(fmaxf(acc.x, acc.y), fmaxf(acc.z, acc.w)) : -INFINITY;
#pragma unroll
        for (int k = 8; k >= 1; k >>= 1)
            m = fmaxf(m, __shfl_xor_sync(0xffffffffu, m, k, 16));
        float s = act ? (__expf(acc.x - m) + __expf(acc.y - m) +
                         __expf(acc.z - m) + __expf(acc.w - m)) : 0.f;
#pragma unroll
        for (int k = 8; k >= 1; k >>= 1)
            s += __shfl_xor_sync(0xffffffffu, s, k, 16);
        float l = m + logf(s);
        if (act) {
            reinterpret_cast<float4*>(outp)[(size_t)row * C4 + lane] =
                make_float4(acc.x - l, acc.y - l, acc.z - l, acc.w - l);
        }
    } else if (act) {
        reinterpret_cast<float4*>(outp)[(size_t)row * C4 + lane] = acc;
    }
}

// ---------------------------------------------------------------------------
// launcher: CSR build on default stream, layer-1 GEMM forked onto s2
// ---------------------------------------------------------------------------
extern "C" void kernel_launch(void* const* d_in, const int* in_sizes, int n_in,
                              void* d_out, int out_size) {
    const float* x  = (const float*)d_in[0];
    const int*   ei = (const int*)d_in[1];
    const float* W1 = (const float*)d_in[2];
    const float* b1 = (const float*)d_in[3];
    const float* Wh = (const float*)d_in[4];
    const float* bh = (const float*)d_in[5];
    const float* W2 = (const float*)d_in[6];
    const float* b2 = (const float*)d_in[7];
    float* out = (float*)d_out;

    int N = in_sizes[0] / IN_C;
    int E = in_sizes[1] / 2;
    const int* src = ei;
    const int* dst = ei + E;

    float* p_h;
    uint2* p_tmph;
    int* p_deg;
    cudaGetSymbolAddress((void**)&p_h, g_h);
    cudaGetSymbolAddress((void**)&p_tmph, g_tmph);
    cudaGetSymbolAddress((void**)&p_deg, g_deg);

    static cudaStream_t s2 = nullptr;
    static cudaEvent_t evFork = nullptr, evJoin = nullptr;
    if (!s2) {
        cudaStreamCreateWithFlags(&s2, cudaStreamNonBlocking);
        cudaEventCreateWithFlags(&evFork, cudaEventDisableTiming);
        cudaEventCreateWithFlags(&evJoin, cudaEventDisableTiming);
    }

    const int T = 256;
    int nb_N = (N + T - 1) / T;
    int nb_E = (E + T - 1) / T;
    int nb_G = (N + 127) / 128;   // gemm: 128 rows/block
    int nb_A = (N + 15) / 16;     // aggregate: 16 rows/block

    // ---- fork: layer-1 GEMM (fp16 out) on s2, overlapping CSR build ----
    cudaEventRecord(evFork, 0);
    cudaStreamWaitEvent(s2, evFork, 0);
    gemmh_kernel<IN_C, HID_C, false><<<nb_G, T, 0, s2>>>(x, W1, p_tmph, N);
    cudaEventRecord(evJoin, s2);

    // ---- CSR build on default stream ----
    cudaMemsetAsync(p_deg, 0, (size_t)N * sizeof(int), 0);
    deg_kernel<<<nb_E, T>>>(dst, E);
    scan_block_kernel<<<SCAN_NB, SCAN_BS>>>(N);   // also computes dinv
    add_off_kernel<<<nb_N, T>>>(N, E);            // folds block-sum prefix in
    fill_kernel<<<nb_E, T>>>(src, dst, E);

    // ---- layer 1: aggregate fp16 messages -> fp32 h ----
    cudaStreamWaitEvent(0, evJoin, 0);
    aggregateh_kernel<HID_C / 4, false><<<nb_A, T>>>(p_tmph, b1, p_h, N);

    // ---- layer 2 ----
    gemmh_kernel<HID_C, HID_C, true><<<nb_G, T>>>(p_h, Wh, p_tmph, N);
    aggregateh_kernel<HID_C / 4, false><<<nb_A, T>>>(p_tmph, bh, p_h, N);

    // ---- layer 3 (40-wide, fp16 messages) + fused log_softmax ----
    gemmh_kernel<HID_C, OUT_C, true><<<nb_G, T>>>(p_h, W2, p_tmph, N);
    aggregateh_kernel<OUT_C / 4, true><<<nb_A, T>>>(p_tmph, b2, out, N);
}